// round 3
// baseline (speedup 1.0000x reference)
#include <cuda_runtime.h>
#include <mma.h>
#include <math.h>

using namespace nvcuda;

#define B_  128
#define C_  2048
#define HW_ 121
#define M_  (B_*HW_)   /* 15488 */

// Scratch (static device arrays — no runtime allocation).
__device__ float g_k[C_*HW_];                 // per-channel circular-conv taps [c][121]
__device__ float g_xf[31719424];              // filtered x, COL-MAJOR: element (m, c) at c*M_ + m

// ---------------------------------------------------------------------------
// K1: build real circular-conv kernel per channel.
// x_filt = Re(IFFT2(ifftshift(fftshift(FFT2(x))*Ms))) == x (circ-conv) k,
// k = IFFT2_std(Mu), Mu[u,v] = Ms[(u+5)%11,(v+5)%11]; k is real (even mask).
// ---------------------------------------------------------------------------
__global__ void build_filters(const float* __restrict__ ft) {
    __shared__ float Mu[121];
    int c = blockIdx.x;
    int t = threadIdx.x;
    float cutoff = fminf(fmaxf(ft[c], 0.05f), 0.5f);
    if (t < 121) {
        int u = t / 11, v = t % 11;
        int a = (u + 5) % 11, b = (v + 5) % 11;
        float dy = (float)(a - 5), dx = (float)(b - 5);
        float dn = sqrtf(dy*dy + dx*dx) / (sqrtf(50.0f) + 1e-6f);
        Mu[t] = 1.0f / (1.0f + expf(-10.0f * (dn - cutoff)));
    }
    __syncthreads();
    if (t < 121) {
        int h = t / 11, w = t % 11;
        float acc = 0.0f;
        for (int u = 0; u < 11; u++) {
            for (int v = 0; v < 11; v++) {
                int ph = (u*h + v*w) % 11;
                acc += Mu[u*11 + v] * cospif(2.0f * (float)ph / 11.0f);
            }
        }
        g_k[c*HW_ + t] = acc / 121.0f;
    }
}

// ---------------------------------------------------------------------------
// K2: apply the spatial filter.  Per channel: XF[b, o] = sum_i T[o,i] * X[b,i]
// (T[o,i] = k[(ho-hi)%11, (wo-wi)%11]).  One block per channel, 256 threads,
// 8x8 register tile per thread (strided: o = tx + 16*j, b = ty + 16*jb).
// Output written to g_xf in col-major [c][b*121+o] -> coalesced.
// ---------------------------------------------------------------------------
__global__ __launch_bounds__(256)
void apply_filter(const float* __restrict__ x) {
    extern __shared__ float sm[];
    float* Ts = sm;                   // 128*121 (rows 121..127 zero-padded)
    float* Xs = sm + 128*HW_;         // 128*121
    float* ks = sm + 2*128*HW_;       // 121
    int c  = blockIdx.x;
    int tx = threadIdx.x, ty = threadIdx.y;
    int tid = ty * 16 + tx;

    if (tid < HW_) ks[tid] = g_k[c*HW_ + tid];
    __syncthreads();

    for (int idx = tid; idx < 128*HW_; idx += 256) {
        int o = idx / HW_, i = idx - o*HW_;
        float v = 0.0f;
        if (o < HW_) {
            int ho = o / 11, wo = o - ho*11;
            int hi = i / 11, wi = i - hi*11;
            int dh = ho - hi; if (dh < 0) dh += 11;
            int dw = wo - wi; if (dw < 0) dw += 11;
            v = ks[dh*11 + dw];
        }
        Ts[idx] = v;
    }
    const float* xc = x + (size_t)c * HW_;
    for (int idx = tid; idx < B_*HW_; idx += 256) {
        int b = idx / HW_, i = idx - b*HW_;
        Xs[idx] = xc[(size_t)b * (C_*HW_) + i];
    }
    __syncthreads();

    float acc[8][8];
    #pragma unroll
    for (int a = 0; a < 8; a++)
        #pragma unroll
        for (int b = 0; b < 8; b++) acc[a][b] = 0.0f;

    for (int i = 0; i < HW_; i++) {
        float xr[8], tr[8];
        #pragma unroll
        for (int jb = 0; jb < 8; jb++) xr[jb] = Xs[(ty + 16*jb)*HW_ + i];
        #pragma unroll
        for (int j = 0; j < 8; j++)  tr[j]  = Ts[(tx + 16*j)*HW_ + i];
        #pragma unroll
        for (int jb = 0; jb < 8; jb++)
            #pragma unroll
            for (int j = 0; j < 8; j++)
                acc[jb][j] += xr[jb] * tr[j];
    }

    float* dst = g_xf + (size_t)c * M_;
    #pragma unroll
    for (int jb = 0; jb < 8; jb++) {
        int b = ty + 16*jb;
        #pragma unroll
        for (int j = 0; j < 8; j++) {
            int o = tx + 16*j;
            if (o < HW_) dst[b*HW_ + o] = acc[jb][j];
        }
    }
}

// ---------------------------------------------------------------------------
// K3: y = XF(15488x2048) * W^T(2048x2048) via wmma TF32, fused
// BN/ReLU/gate/residual epilogue writing out in [b][o][hw] layout.
// Block tile 128x128, Ktile 16, 8 warps (4x2) each 32x64, double-buffered.
// ---------------------------------------------------------------------------
#define LDA  132
#define LDB  20
#define ABUF (LDA*16)     /* 2112 floats */
#define BBUF (LDB*128)    /* 2560 floats */
#define NKT  (C_/16)      /* 128 */

__global__ __launch_bounds__(256)
void gemm_fused(const float* __restrict__ x,
                const float* __restrict__ Wg,
                const float* __restrict__ cb,
                const float* __restrict__ ga,
                const float* __restrict__ be,
                const float* __restrict__ me,
                const float* __restrict__ va,
                const float* __restrict__ gate,
                float* __restrict__ out) {
    extern __shared__ float sm[];
    float* As = sm;               // 2 * ABUF  (col-major m x k tile)
    float* Bs = sm + 2*ABUF;      // 2 * BBUF  (col-major k x n tile)

    int bx = blockIdx.x, by = blockIdx.y;
    int tid = threadIdx.x;
    int wid = tid >> 5;
    int wm = (wid & 3) * 32;
    int wn = (wid >> 2) * 64;

    const float* Ag = g_xf + bx * 128;                  // (m,k) at k*M_ + m
    const float* Bg = Wg + (size_t)(by * 128) * C_;     // W[n][k], k contiguous

    wmma::fragment<wmma::accumulator, 16, 16, 8, float> acc[2][4];
    #pragma unroll
    for (int mi = 0; mi < 2; mi++)
        #pragma unroll
        for (int ni = 0; ni < 4; ni++) wmma::fill_fragment(acc[mi][ni], 0.0f);

    float4 av[2], bv[2];

    auto ldg = [&](int t) {
        int k0 = t * 16;
        #pragma unroll
        for (int q = 0; q < 2; q++) {
            int idx = tid + q * 256;
            int kk = idx >> 5, mm = (idx & 31) * 4;
            av[q] = *reinterpret_cast<const float4*>(&Ag[(size_t)(k0 + kk) * M_ + mm]);
            int n = idx >> 2, kq = (idx & 3) * 4;
            bv[q] = *reinterpret_cast<const float4*>(&Bg[(size_t)n * C_ + k0 + kq]);
        }
    };
    auto sts = [&](int buf) {
        #pragma unroll
        for (int q = 0; q < 2; q++) {
            int idx = tid + q * 256;
            int kk = idx >> 5, mm = (idx & 31) * 4;
            float4 a = av[q];
            a.x = wmma::__float_to_tf32(a.x); a.y = wmma::__float_to_tf32(a.y);
            a.z = wmma::__float_to_tf32(a.z); a.w = wmma::__float_to_tf32(a.w);
            *reinterpret_cast<float4*>(&As[buf*ABUF + kk*LDA + mm]) = a;
            int n = idx >> 2, kq = (idx & 3) * 4;
            float4 b = bv[q];
            b.x = wmma::__float_to_tf32(b.x); b.y = wmma::__float_to_tf32(b.y);
            b.z = wmma::__float_to_tf32(b.z); b.w = wmma::__float_to_tf32(b.w);
            *reinterpret_cast<float4*>(&Bs[buf*BBUF + n*LDB + kq]) = b;
        }
    };
    auto comp = [&](int buf) {
        #pragma unroll
        for (int ks = 0; ks < 2; ks++) {
            wmma::fragment<wmma::matrix_a, 16, 16, 8, wmma::precision::tf32, wmma::col_major> af[2];
            wmma::fragment<wmma::matrix_b, 16, 16, 8, wmma::precision::tf32, wmma::col_major> bf[4];
            #pragma unroll
            for (int mi = 0; mi < 2; mi++)
                wmma::load_matrix_sync(af[mi], &As[buf*ABUF + (wm + mi*16) + (ks*8)*LDA], LDA);
            #pragma unroll
            for (int ni = 0; ni < 4; ni++)
                wmma::load_matrix_sync(bf[ni], &Bs[buf*BBUF + ks*8 + (wn + ni*16)*LDB], LDB);
            #pragma unroll
            for (int mi = 0; mi < 2; mi++)
                #pragma unroll
                for (int ni = 0; ni < 4; ni++)
                    wmma::mma_sync(acc[mi][ni], af[mi], bf[ni], acc[mi][ni]);
        }
    };

    ldg(0); sts(0); __syncthreads();
    int buf = 0;
    for (int t = 0; t < NKT; t++) {
        if (t + 1 < NKT) ldg(t + 1);
        comp(buf);
        __syncthreads();
        if (t + 1 < NKT) { sts(buf ^ 1); buf ^= 1; __syncthreads(); }
    }
    __syncthreads();

    // Epilogue: stash tile in smem (col-major), then BN + ReLU + gate + residual.
    float* Ep   = sm;                  // 132*128 floats, (mm,nn) at mm + nn*132
    float* s_sc = sm + 132*128;
    float* s_bi = s_sc + 128;
    #pragma unroll
    for (int mi = 0; mi < 2; mi++)
        #pragma unroll
        for (int ni = 0; ni < 4; ni++)
            wmma::store_matrix_sync(&Ep[(wm + mi*16) + (size_t)(wn + ni*16) * 132],
                                    acc[mi][ni], 132, wmma::mem_col_major);
    if (tid < 128) {
        int o = by * 128 + tid;
        float sc = ga[o] * rsqrtf(va[o] + 1e-5f);
        s_sc[tid] = sc;
        s_bi[tid] = (cb[o] - me[o]) * sc + be[o];
    }
    __syncthreads();

    float g = fminf(fmaxf(gate[0], 0.0f), 1.0f);
    #pragma unroll 4
    for (int q = 0; q < 64; q++) {
        int idx = tid + q * 256;
        int nn = idx >> 7, mm = idx & 127;
        float v = Ep[mm + nn * 132];
        v = fmaxf(v * s_sc[nn] + s_bi[nn], 0.0f);
        int m = bx * 128 + mm;
        int b = m / 121, hw = m - b * 121;
        size_t oi = (size_t)b * (C_*HW_) + (size_t)(by * 128 + nn) * HW_ + hw;
        out[oi] = x[oi] + g * v;
    }
}

// ---------------------------------------------------------------------------
extern "C" void kernel_launch(void* const* d_in, const int* in_sizes, int n_in,
                              void* d_out, int out_size) {
    const float* x    = (const float*)d_in[0];
    const float* ft   = (const float*)d_in[1];
    const float* gate = (const float*)d_in[2];
    const float* w    = (const float*)d_in[3];
    const float* cbias= (const float*)d_in[4];
    const float* ga   = (const float*)d_in[5];
    const float* be   = (const float*)d_in[6];
    const float* me   = (const float*)d_in[7];
    const float* va   = (const float*)d_in[8];
    float* out = (float*)d_out;

    build_filters<<<C_, 128>>>(ft);

    size_t smem2 = (size_t)(2*128*HW_ + 128) * sizeof(float);   // ~124.4 KB
    cudaFuncSetAttribute(apply_filter, cudaFuncAttributeMaxDynamicSharedMemorySize, (int)smem2);
    apply_filter<<<C_, dim3(16,16), smem2>>>(x);

    size_t smem3 = (size_t)(132*128 + 256) * sizeof(float);     // ~68.6 KB (>= pipeline bufs)
    cudaFuncSetAttribute(gemm_fused, cudaFuncAttributeMaxDynamicSharedMemorySize, (int)smem3);
    gemm_fused<<<dim3(121,16), 256, smem3>>>(x, w, cbias, ga, be, me, va, gate, out);
}

// round 4
// speedup vs baseline: 1.0021x; 1.0021x over previous
#include <cuda_runtime.h>
#include <mma.h>
#include <math.h>

using namespace nvcuda;

#define B_  128
#define C_  2048
#define HW_ 121
#define M_  (B_*HW_)   /* 15488 */

// Scratch (static device arrays — no runtime allocation).
__device__ float g_k[C_*HW_];                 // per-channel circular-conv taps [c][121]
__device__ float g_xf[31719424];              // filtered x, COL-MAJOR: element (m, c) at c*M_ + m

// ---------------------------------------------------------------------------
// K1: build real circular-conv kernel per channel.
// x_filt = Re(IFFT2(ifftshift(fftshift(FFT2(x))*Ms))) == x (circ-conv) k,
// k = IFFT2_std(Mu), Mu[u,v] = Ms[(u+5)%11,(v+5)%11]; k is real (even mask).
// ---------------------------------------------------------------------------
__global__ void build_filters(const float* __restrict__ ft) {
    __shared__ float Mu[121];
    int c = blockIdx.x;
    int t = threadIdx.x;
    float cutoff = fminf(fmaxf(ft[c], 0.05f), 0.5f);
    if (t < 121) {
        int u = t / 11, v = t % 11;
        int a = (u + 5) % 11, b = (v + 5) % 11;
        float dy = (float)(a - 5), dx = (float)(b - 5);
        float dn = sqrtf(dy*dy + dx*dx) / (sqrtf(50.0f) + 1e-6f);
        Mu[t] = 1.0f / (1.0f + expf(-10.0f * (dn - cutoff)));
    }
    __syncthreads();
    if (t < 121) {
        int h = t / 11, w = t % 11;
        float acc = 0.0f;
        for (int u = 0; u < 11; u++) {
            for (int v = 0; v < 11; v++) {
                int ph = (u*h + v*w) % 11;
                acc += Mu[u*11 + v] * cospif(2.0f * (float)ph / 11.0f);
            }
        }
        g_k[c*HW_ + t] = acc / 121.0f;
    }
}

// ---------------------------------------------------------------------------
// K2: apply the spatial filter.  Per channel: XF[b, o] = sum_i T[o,i] * X[b,i]
// (T[o,i] = k[(ho-hi)%11, (wo-wi)%11]).  One block per channel, 256 threads,
// 8x8 register tile per thread (strided: o = tx + 16*j, b = ty + 16*jb).
// Output written to g_xf in col-major [c][b*121+o] -> coalesced.
// ---------------------------------------------------------------------------
__global__ __launch_bounds__(256)
void apply_filter(const float* __restrict__ x) {
    extern __shared__ float sm[];
    float* Ts = sm;                   // 128*121 (rows 121..127 zero-padded)
    float* Xs = sm + 128*HW_;         // 128*121
    float* ks = sm + 2*128*HW_;       // 121
    int c  = blockIdx.x;
    int tx = threadIdx.x, ty = threadIdx.y;
    int tid = ty * 16 + tx;

    if (tid < HW_) ks[tid] = g_k[c*HW_ + tid];
    __syncthreads();

    for (int idx = tid; idx < 128*HW_; idx += 256) {
        int o = idx / HW_, i = idx - o*HW_;
        float v = 0.0f;
        if (o < HW_) {
            int ho = o / 11, wo = o - ho*11;
            int hi = i / 11, wi = i - hi*11;
            int dh = ho - hi; if (dh < 0) dh += 11;
            int dw = wo - wi; if (dw < 0) dw += 11;
            v = ks[dh*11 + dw];
        }
        Ts[idx] = v;
    }
    const float* xc = x + (size_t)c * HW_;
    for (int idx = tid; idx < B_*HW_; idx += 256) {
        int b = idx / HW_, i = idx - b*HW_;
        Xs[idx] = xc[(size_t)b * (C_*HW_) + i];
    }
    __syncthreads();

    float acc[8][8];
    #pragma unroll
    for (int a = 0; a < 8; a++)
        #pragma unroll
        for (int b = 0; b < 8; b++) acc[a][b] = 0.0f;

    for (int i = 0; i < HW_; i++) {
        float xr[8], tr[8];
        #pragma unroll
        for (int jb = 0; jb < 8; jb++) xr[jb] = Xs[(ty + 16*jb)*HW_ + i];
        #pragma unroll
        for (int j = 0; j < 8; j++)  tr[j]  = Ts[(tx + 16*j)*HW_ + i];
        #pragma unroll
        for (int jb = 0; jb < 8; jb++)
            #pragma unroll
            for (int j = 0; j < 8; j++)
                acc[jb][j] += xr[jb] * tr[j];
    }

    float* dst = g_xf + (size_t)c * M_;
    #pragma unroll
    for (int jb = 0; jb < 8; jb++) {
        int b = ty + 16*jb;
        #pragma unroll
        for (int j = 0; j < 8; j++) {
            int o = tx + 16*j;
            if (o < HW_) dst[b*HW_ + o] = acc[jb][j];
        }
    }
}

// ---------------------------------------------------------------------------
// K3: y = XF(15488x2048) * W^T(2048x2048) via wmma TF32, fused
// BN/ReLU/gate/residual epilogue writing out in [b][o][hw] layout.
// Block tile 128x128, Ktile 16, 8 warps (4x2) each 32x64, double-buffered.
// ---------------------------------------------------------------------------
#define LDA  132
#define LDB  20
#define ABUF (LDA*16)     /* 2112 floats */
#define BBUF (LDB*128)    /* 2560 floats */
#define NKT  (C_/16)      /* 128 */

__global__ __launch_bounds__(256)
void gemm_fused(const float* __restrict__ x,
                const float* __restrict__ Wg,
                const float* __restrict__ cb,
                const float* __restrict__ ga,
                const float* __restrict__ be,
                const float* __restrict__ me,
                const float* __restrict__ va,
                const float* __restrict__ gate,
                float* __restrict__ out) {
    extern __shared__ float sm[];
    float* As = sm;               // 2 * ABUF  (col-major m x k tile)
    float* Bs = sm + 2*ABUF;      // 2 * BBUF  (col-major k x n tile)

    int bx = blockIdx.x, by = blockIdx.y;
    int tid = threadIdx.x;
    int wid = tid >> 5;
    int wm = (wid & 3) * 32;
    int wn = (wid >> 2) * 64;

    const float* Ag = g_xf + bx * 128;                  // (m,k) at k*M_ + m
    const float* Bg = Wg + (size_t)(by * 128) * C_;     // W[n][k], k contiguous

    wmma::fragment<wmma::accumulator, 16, 16, 8, float> acc[2][4];
    #pragma unroll
    for (int mi = 0; mi < 2; mi++)
        #pragma unroll
        for (int ni = 0; ni < 4; ni++) wmma::fill_fragment(acc[mi][ni], 0.0f);

    float4 av[2], bv[2];

    auto ldg = [&](int t) {
        int k0 = t * 16;
        #pragma unroll
        for (int q = 0; q < 2; q++) {
            int idx = tid + q * 256;
            int kk = idx >> 5, mm = (idx & 31) * 4;
            av[q] = *reinterpret_cast<const float4*>(&Ag[(size_t)(k0 + kk) * M_ + mm]);
            int n = idx >> 2, kq = (idx & 3) * 4;
            bv[q] = *reinterpret_cast<const float4*>(&Bg[(size_t)n * C_ + k0 + kq]);
        }
    };
    auto sts = [&](int buf) {
        #pragma unroll
        for (int q = 0; q < 2; q++) {
            int idx = tid + q * 256;
            int kk = idx >> 5, mm = (idx & 31) * 4;
            float4 a = av[q];
            a.x = wmma::__float_to_tf32(a.x); a.y = wmma::__float_to_tf32(a.y);
            a.z = wmma::__float_to_tf32(a.z); a.w = wmma::__float_to_tf32(a.w);
            *reinterpret_cast<float4*>(&As[buf*ABUF + kk*LDA + mm]) = a;
            int n = idx >> 2, kq = (idx & 3) * 4;
            float4 b = bv[q];
            b.x = wmma::__float_to_tf32(b.x); b.y = wmma::__float_to_tf32(b.y);
            b.z = wmma::__float_to_tf32(b.z); b.w = wmma::__float_to_tf32(b.w);
            *reinterpret_cast<float4*>(&Bs[buf*BBUF + n*LDB + kq]) = b;
        }
    };
    auto comp = [&](int buf) {
        #pragma unroll
        for (int ks = 0; ks < 2; ks++) {
            wmma::fragment<wmma::matrix_a, 16, 16, 8, wmma::precision::tf32, wmma::col_major> af[2];
            wmma::fragment<wmma::matrix_b, 16, 16, 8, wmma::precision::tf32, wmma::col_major> bf[4];
            #pragma unroll
            for (int mi = 0; mi < 2; mi++)
                wmma::load_matrix_sync(af[mi], &As[buf*ABUF + (wm + mi*16) + (ks*8)*LDA], LDA);
            #pragma unroll
            for (int ni = 0; ni < 4; ni++)
                wmma::load_matrix_sync(bf[ni], &Bs[buf*BBUF + ks*8 + (wn + ni*16)*LDB], LDB);
            #pragma unroll
            for (int mi = 0; mi < 2; mi++)
                #pragma unroll
                for (int ni = 0; ni < 4; ni++)
                    wmma::mma_sync(acc[mi][ni], af[mi], bf[ni], acc[mi][ni]);
        }
    };

    ldg(0); sts(0); __syncthreads();
    int buf = 0;
    for (int t = 0; t < NKT; t++) {
        if (t + 1 < NKT) ldg(t + 1);
        comp(buf);
        __syncthreads();
        if (t + 1 < NKT) { sts(buf ^ 1); buf ^= 1; __syncthreads(); }
    }
    __syncthreads();

    // Epilogue: stash tile in smem (col-major), then BN + ReLU + gate + residual.
    float* Ep   = sm;                  // 132*128 floats, (mm,nn) at mm + nn*132
    float* s_sc = sm + 132*128;
    float* s_bi = s_sc + 128;
    #pragma unroll
    for (int mi = 0; mi < 2; mi++)
        #pragma unroll
        for (int ni = 0; ni < 4; ni++)
            wmma::store_matrix_sync(&Ep[(wm + mi*16) + (size_t)(wn + ni*16) * 132],
                                    acc[mi][ni], 132, wmma::mem_col_major);
    if (tid < 128) {
        int o = by * 128 + tid;
        float sc = ga[o] * rsqrtf(va[o] + 1e-5f);
        s_sc[tid] = sc;
        s_bi[tid] = (cb[o] - me[o]) * sc + be[o];
    }
    __syncthreads();

    float g = fminf(fmaxf(gate[0], 0.0f), 1.0f);
    #pragma unroll 4
    for (int q = 0; q < 64; q++) {
        int idx = tid + q * 256;
        int nn = idx >> 7, mm = idx & 127;
        float v = Ep[mm + nn * 132];
        v = fmaxf(v * s_sc[nn] + s_bi[nn], 0.0f);
        int m = bx * 128 + mm;
        int b = m / 121, hw = m - b * 121;
        size_t oi = (size_t)b * (C_*HW_) + (size_t)(by * 128 + nn) * HW_ + hw;
        out[oi] = x[oi] + g * v;
    }
}

// ---------------------------------------------------------------------------
extern "C" void kernel_launch(void* const* d_in, const int* in_sizes, int n_in,
                              void* d_out, int out_size) {
    const float* x    = (const float*)d_in[0];
    const float* ft   = (const float*)d_in[1];
    const float* gate = (const float*)d_in[2];
    const float* w    = (const float*)d_in[3];
    const float* cbias= (const float*)d_in[4];
    const float* ga   = (const float*)d_in[5];
    const float* be   = (const float*)d_in[6];
    const float* me   = (const float*)d_in[7];
    const float* va   = (const float*)d_in[8];
    float* out = (float*)d_out;

    build_filters<<<C_, 128>>>(ft);

    size_t smem2 = (size_t)(2*128*HW_ + 128) * sizeof(float);   // ~124.4 KB
    cudaFuncSetAttribute(apply_filter, cudaFuncAttributeMaxDynamicSharedMemorySize, (int)smem2);
    apply_filter<<<C_, dim3(16,16), smem2>>>(x);

    size_t smem3 = (size_t)(132*128 + 256) * sizeof(float);     // ~68.6 KB (>= pipeline bufs)
    cudaFuncSetAttribute(gemm_fused, cudaFuncAttributeMaxDynamicSharedMemorySize, (int)smem3);
    gemm_fused<<<dim3(121,16), 256, smem3>>>(x, w, cbias, ga, be, me, va, gate, out);
}